// round 16
// baseline (speedup 1.0000x reference)
#include <cuda_runtime.h>
#include <cuda_fp16.h>
#include <math.h>
#include <stdint.h>

// ---- arch-feature gate: tcgen05 only exists in the sm_103a/sm_100a passes ----
#if defined(__CUDA_ARCH_FEAT_SM103_ALL) || defined(__CUDA_ARCH_FEAT_SM100_ALL) || defined(__CUDA_ARCH_FEAT_SM101_ALL)
#  define HAS_TC 1
#elif defined(__CUDA_ARCH_HAS_FEATURE__)
#  if __CUDA_ARCH_HAS_FEATURE__(SM103_ALL) || __CUDA_ARCH_HAS_FEATURE__(SM100_ALL)
#    define HAS_TC 1
#  else
#    define HAS_TC 0
#  endif
#else
#  define HAS_TC 0
#endif

#define NBATCH 2
#define C_DIM  768
#define S_DIM  4096
#define L_DIM  1024
#define D_DIM  96
#define T_DIM  384
#define F_DIM  1536
#define NHEAD  16

// ------------- scratch (__device__ globals; no allocation allowed) -------------
static __device__ float  g_xTr[NBATCH*S_DIM*C_DIM];  // x^T raw fp32 [n][s][c]
static __device__ __align__(16) __half g_xT [NBATCH*S_DIM*C_DIM];  // x^T fp16
static __device__ __align__(16) __half g_xtT[NBATCH*L_DIM*T_DIM];  // x_t^T fp16
static __device__ __align__(16) __half g_qt [NBATCH*S_DIM*C_DIM];  // q_t fp16
static __device__ __align__(16) __half g_kt [NBATCH*L_DIM*C_DIM];  // k_t fp16
static __device__ __align__(16) __half g_yt [NBATCH*S_DIM*C_DIM];  // y^T fp16
static __device__ __align__(16) __half g_ht [NBATCH*S_DIM*F_DIM];  // relu(W1 y) fp16
static __device__ __align__(16) __half g_v3h[NBATCH*C_DIM*L_DIM];  // v*tm^3 fp16
// fp16 copies of weights, concatenated
#define WV_OFF 0
#define WK_OFF (C_DIM*T_DIM)
#define WQ_OFF (2*C_DIM*T_DIM)
#define W1_OFF (2*C_DIM*T_DIM + C_DIM*C_DIM)
#define W2_OFF (W1_OFF + 2*C_DIM*C_DIM)
#define W_TOT  (W2_OFF + 2*C_DIM*C_DIM)
static __device__ __align__(16) __half g_w16[W_TOT];

// ---------------------------- PTX helpers ----------------------------
__device__ __forceinline__ uint32_t smem_u32(const void* p){
    uint32_t a;
    asm("{ .reg .u64 t; cvta.to.shared.u64 t, %1; cvt.u32.u64 %0, t; }":"=r"(a):"l"(p));
    return a;
}
__device__ __forceinline__ uint32_t elect_one(){
    uint32_t r;
    asm volatile("{\n\t.reg .pred p;\n\telect.sync _|p, 0xFFFFFFFF;\n\tselp.b32 %0, 1, 0, p;\n\t}":"=r"(r));
    return r;
}
__device__ __forceinline__ uint32_t pack_f16(float lo, float hi){
    uint32_t r; asm("cvt.rn.f16x2.f32 %0, %1, %2;":"=r"(r):"f"(hi),"f"(lo));
    return r;
}
#define SWZ(o) ((o) ^ ((((uint32_t)(o))>>3)&0x70u))

__device__ __forceinline__ void cp16(uint32_t dst, const void* src){
    asm volatile("cp.async.cg.shared.global [%0], [%1], 16;"::"r"(dst),"l"(src):"memory");
}
__device__ __forceinline__ void cp_commit(){
    asm volatile("cp.async.commit_group;":::"memory");
}
template<int N> __device__ __forceinline__ void cp_wait(){
    asm volatile("cp.async.wait_group %0;"::"n"(N):"memory");
}
__device__ __forceinline__ void mbar_init(uint32_t a, uint32_t cnt){
    asm volatile("mbarrier.init.shared.b64 [%0], %1;"::"r"(a),"r"(cnt):"memory");
}
__device__ __forceinline__ void mbar_wait(uint32_t a, uint32_t ph){
    asm volatile(
        "{\n\t.reg .pred P;\n\t"
        "WL%=:\n\t"
        "mbarrier.try_wait.parity.acquire.cta.shared::cta.b64 P, [%0], %1;\n\t"
        "@P bra WD%=;\n\t"
        "bra WL%=;\n\t"
        "WD%=:\n\t}"
        ::"r"(a),"r"(ph):"memory");
}
__device__ __forceinline__ void tc_commit(uint32_t mb){
#if HAS_TC
    asm volatile("tcgen05.commit.cta_group::1.mbarrier::arrive::one.shared::cluster.b64 [%0];"
                 ::"r"(mb):"memory");
#endif
}
__device__ __forceinline__ void tc_alloc(uint32_t smem_dst, uint32_t ncols){
#if HAS_TC
    asm volatile("tcgen05.alloc.cta_group::1.sync.aligned.shared::cta.b32 [%0], %1;"
                 ::"r"(smem_dst),"r"(ncols):"memory");
#endif
}
__device__ __forceinline__ void tc_dealloc(uint32_t tmem, uint32_t ncols){
#if HAS_TC
    asm volatile("tcgen05.dealloc.cta_group::1.sync.aligned.b32 %0, %1;"::"r"(tmem),"r"(ncols));
#endif
}
__device__ __forceinline__ void tc_relinquish(){
#if HAS_TC
    asm volatile("tcgen05.relinquish_alloc_permit.cta_group::1.sync.aligned;");
#endif
}
__device__ __forceinline__ void fence_after(){
#if HAS_TC
    asm volatile("tcgen05.fence::after_thread_sync;":::"memory");
#endif
}
__device__ __forceinline__ void fence_proxy(){
    asm volatile("fence.proxy.async.shared::cta;":::"memory");
}
__device__ __forceinline__ void tc_wait_ld(){
#if HAS_TC
    asm volatile("tcgen05.wait::ld.sync.aligned;":::"memory");
#endif
}
__device__ __forceinline__ uint64_t mk_desc(uint32_t addr){
    const uint64_t BASE = (uint64_t(2)<<61)|(uint64_t(1)<<46)|(uint64_t(64)<<32)|(uint64_t(1)<<16);
    return BASE | ((uint64_t)(addr>>4) & 0x3FFFull);
}
// fp16 MMA (kind::f16, atype=btype=F16=0, dtype=F32)
__device__ __forceinline__ void mma_f16(uint32_t d, uint64_t ad, uint64_t bd, uint32_t idesc, uint32_t en){
#if HAS_TC
    asm volatile(
        "{\n\t.reg .pred p;\n\tsetp.ne.u32 p, %5, 0;\n\t"
        "tcgen05.mma.cta_group::1.kind::f16 [%0], %1, %2, %3, {%4,%4,%4,%4}, p;\n\t}"
        :: "r"(d), "l"(ad), "l"(bd), "r"(idesc), "r"(0u), "r"(en) : "memory");
#endif
}
#if HAS_TC
#define LDTM32(r, a) \
    asm volatile( \
        "tcgen05.ld.sync.aligned.32x32b.x32.b32 " \
        "{%0, %1, %2, %3, %4, %5, %6, %7, " \
        " %8, %9, %10, %11, %12, %13, %14, %15, " \
        " %16, %17, %18, %19, %20, %21, %22, %23, " \
        " %24, %25, %26, %27, %28, %29, %30, %31}, [%32];" \
        : "=r"((r)[0]),  "=r"((r)[1]),  "=r"((r)[2]),  "=r"((r)[3]), \
          "=r"((r)[4]),  "=r"((r)[5]),  "=r"((r)[6]),  "=r"((r)[7]), \
          "=r"((r)[8]),  "=r"((r)[9]),  "=r"((r)[10]), "=r"((r)[11]), \
          "=r"((r)[12]), "=r"((r)[13]), "=r"((r)[14]), "=r"((r)[15]), \
          "=r"((r)[16]), "=r"((r)[17]), "=r"((r)[18]), "=r"((r)[19]), \
          "=r"((r)[20]), "=r"((r)[21]), "=r"((r)[22]), "=r"((r)[23]), \
          "=r"((r)[24]), "=r"((r)[25]), "=r"((r)[26]), "=r"((r)[27]), \
          "=r"((r)[28]), "=r"((r)[29]), "=r"((r)[30]), "=r"((r)[31]) \
        : "r"(a))
#endif

// ---------------------------- prep (fused transposes + cvt) ----------------------------
template<bool DUAL>
__device__ __forceinline__ void transpose_body(const float* __restrict__ src,
                                               __half* __restrict__ dst16, float* __restrict__ draw,
                                               int R, int Cc, int bx, int by, int nb, int tid){
    __shared__ float t[32][33];
    src   += (size_t)nb*R*Cc;
    dst16 += (size_t)nb*R*Cc;
    if (DUAL) draw += (size_t)nb*R*Cc;
    int c0 = bx*32, r0 = by*32;
    int x = tid & 31, y = tid >> 5;
#pragma unroll
    for (int i = 0; i < 32; i += 8)
        t[y+i][x] = src[(size_t)(r0+y+i)*Cc + c0 + x];
    __syncthreads();
#pragma unroll
    for (int i = 0; i < 32; i += 8){
        float v = t[x][y+i];
        dst16[(size_t)(c0+y+i)*R + r0 + x] = __float2half_rn(v);
        if (DUAL) draw[(size_t)(c0+y+i)*R + r0 + x] = v;
    }
}

#define TRX_BLKS  (S_DIM/32 * C_DIM/32 * NBATCH)   // 6144
#define TRXT_BLKS (L_DIM/32 * T_DIM/32 * NBATCH)   // 768
#define PREP_TOTAL (2*(C_DIM*T_DIM/4) + C_DIM*C_DIM/4 + 2*(2*C_DIM*C_DIM/4))
#define PREP_BLKS ((PREP_TOTAL + 255)/256)
#define PREPALL_GRID (TRX_BLKS + TRXT_BLKS + PREP_BLKS)

__global__ void __launch_bounds__(256) prep_all(
    const float* __restrict__ x, const float* __restrict__ xt,
    const float* __restrict__ Wv, const float* __restrict__ Wk, const float* __restrict__ Wq,
    const float* __restrict__ W1, const float* __restrict__ W2)
{
    int b = blockIdx.x, tid = threadIdx.x;
    if (b < TRX_BLKS){
        transpose_body<true>(x, g_xT, g_xTr, C_DIM, S_DIM, b % (S_DIM/32),
                             (b/(S_DIM/32)) % (C_DIM/32), b/(S_DIM/32 * C_DIM/32), tid);
        return;
    }
    b -= TRX_BLKS;
    if (b < TRXT_BLKS){
        transpose_body<false>(xt, g_xtT, nullptr, T_DIM, L_DIM, b % (L_DIM/32),
                              (b/(L_DIM/32)) % (T_DIM/32), b/(L_DIM/32 * T_DIM/32), tid);
        return;
    }
    b -= TRXT_BLKS;
    int j = b*256 + tid;
    const int NVT = C_DIM*T_DIM/4, NQ = C_DIM*C_DIM/4, NF = 2*C_DIM*C_DIM/4;
    const float* src; __half* dst;
    if (j < NVT){ src = Wv; dst = g_w16 + WV_OFF; }
    else if ((j -= NVT) < NVT){ src = Wk; dst = g_w16 + WK_OFF; }
    else if ((j -= NVT) < NQ ){ src = Wq; dst = g_w16 + WQ_OFF; }
    else if ((j -= NQ ) < NF ){ src = W1; dst = g_w16 + W1_OFF; }
    else if ((j -= NF ) < NF ){ src = W2; dst = g_w16 + W2_OFF; }
    else return;
    float4 v = ((const float4*)src)[j];
    uint2 o;
    o.x = pack_f16(v.x, v.y);
    o.y = pack_f16(v.z, v.w);
    ((uint2*)dst)[j] = o;
}

// ---------------------------- generic tcgen05 fp16 GEMM ----------------------------
// modes 0,1: BN=128; modes 2,5,6: BN=256 (halves A-side L2 traffic; per-SM L2-port bound).
// K-tile=64 halves, 2 stages distance-1. SMEM 97KB -> 2 CTAs/SM (TMEM 2x256=512 fits).
#define SM_TMEM 0
#define SM_MB   16
#define SM_A(s) (1024u  + (uint32_t)(s)*16384u)
#define SM_B(s) (33792u + (uint32_t)(s)*32768u)
#define SMEM_BYTES 99328

struct GP {
    const void* A; const void* B; void* C;
    const float* tm; const float* xa;
};

template<int MODE>
__device__ __forceinline__ void gemm_body(const GP& g, int bxx, int byy, int nb,
                                          char* smem, uint32_t sb)
{
    const int tid = threadIdx.x, wid = tid >> 5, lid = tid & 31;
    constexpr int NCOL = (MODE==0||MODE==1) ? 128 : 256;
    constexpr int NB = NCOL/32;                  // B cp16 per thread (NCOL rows x 128B / 4KB)
    const int m0 = byy*128, n0 = bxx*NCOL;
    constexpr int KK = (MODE==0||MODE==1) ? T_DIM : (MODE==2||MODE==5) ? C_DIM : F_DIM;
    constexpr int NT = KK / 64;
    constexpr uint32_t IDESC = (1u<<4)|((uint32_t)(NCOL/8)<<17)|(8u<<24);   // f16 in, f32 acc

    const char* Apb = nullptr; const char* Bpb = nullptr;
    uint32_t ldA = 0, ldB = 0;
    if constexpr (MODE==0){ Apb=(const char*)g.A + ((size_t)nb*L_DIM*T_DIM+(size_t)m0*T_DIM)*2; ldA=T_DIM*2;
                            Bpb=(const char*)g.B + (size_t)n0*T_DIM*2; ldB=T_DIM*2; }
    if constexpr (MODE==1){ Apb=(const char*)g.A + (size_t)m0*T_DIM*2; ldA=T_DIM*2;
                            Bpb=(const char*)g.B + ((size_t)nb*L_DIM*T_DIM+(size_t)n0*T_DIM)*2; ldB=T_DIM*2; }
    if constexpr (MODE==2){ Apb=(const char*)g.A + ((size_t)nb*S_DIM*C_DIM+(size_t)m0*C_DIM)*2; ldA=C_DIM*2;
                            Bpb=(const char*)g.B + (size_t)n0*C_DIM*2; ldB=C_DIM*2; }
    if constexpr (MODE==5){ Apb=(const char*)g.A + ((size_t)nb*S_DIM*C_DIM+(size_t)m0*C_DIM)*2; ldA=C_DIM*2;
                            Bpb=(const char*)g.B + (size_t)n0*C_DIM*2; ldB=C_DIM*2; }
    if constexpr (MODE==6){ Apb=(const char*)g.A + (size_t)m0*F_DIM*2; ldA=F_DIM*2;
                            Bpb=(const char*)g.B + ((size_t)nb*S_DIM*F_DIM+(size_t)n0*F_DIM)*2; ldB=F_DIM*2; }

    // hoisted per-thread fill offsets (loop-invariant)
    uint32_t dstA[4], srcA[4], dstB[NB], srcB[NB];
#pragma unroll
    for (int k2 = 0; k2 < 4; k2++){
        int idx = tid + k2*256, row = idx >> 3, c4 = idx & 7;
        dstA[k2] = SWZ((uint32_t)row*128u + (uint32_t)c4*16u);
        srcA[k2] = (uint32_t)row*ldA + (uint32_t)c4*16u;
    }
#pragma unroll
    for (int k2 = 0; k2 < NB; k2++){
        int idx = tid + k2*256, row = idx >> 3, c4 = idx & 7;
        dstB[k2] = SWZ((uint32_t)row*128u + (uint32_t)c4*16u);
        srcB[k2] = (uint32_t)row*ldB + (uint32_t)c4*16u;
    }
    auto fill_tile = [&](int tt, int s){
        const char* a = Apb + (size_t)tt*128;
        const char* b = Bpb + (size_t)tt*128;
        const uint32_t ba = sb + SM_A(s), bb = sb + SM_B(s);
#pragma unroll
        for (int k2 = 0; k2 < 4; k2++) cp16(ba + dstA[k2], a + srcA[k2]);
#pragma unroll
        for (int k2 = 0; k2 < NB; k2++) cp16(bb + dstB[k2], b + srcB[k2]);
    };

#if HAS_TC
    if (wid == 0) tc_alloc(sb + SM_TMEM, NCOL);
    if (tid == 0){
        mbar_init(sb + SM_MB,      1);
        mbar_init(sb + SM_MB + 16, 1);
    }
    __syncthreads();
    uint32_t tmem;
    asm volatile("ld.shared.b32 %0, [%1];" : "=r"(tmem) : "r"(sb + SM_TMEM));
    if (wid == 0) tc_relinquish();

    int ph[2] = {0,0};
    fill_tile(0, 0); cp_commit();

    for (int t = 0; t < NT; t++){
        const int nf = t + 1;
        if (nf < NT){
            const int s = nf & 1;
            if (nf >= 2){ mbar_wait(sb + SM_MB + (uint32_t)s*16u, (uint32_t)ph[s]); ph[s] ^= 1; }
            fill_tile(nf, s);
        }
        cp_commit();
        cp_wait<1>();
        __syncthreads();
        const int sc = t & 1;
        if (wid == 0 && elect_one()){
            fence_proxy();
            uint64_t ad = mk_desc(sb + SM_A(sc));
            uint64_t bd = mk_desc(sb + SM_B(sc));
#pragma unroll
            for (int c = 0; c < 4; c++)           // 4 x K=16 per 64-K tile
                mma_f16(tmem, ad + c*2, bd + c*2, IDESC, (t > 0 || c > 0) ? 1u : 0u);
            tc_commit(sb + SM_MB + (uint32_t)sc*16u);
        }
    }
    {
        const int sl = (NT - 1) & 1;
        mbar_wait(sb + SM_MB + (uint32_t)sl*16u, (uint32_t)ph[sl]);
    }
    fence_after();
#else
    float facc[NCOL];
#pragma unroll
    for (int j = 0; j < NCOL; j++) facc[j] = 0.f;
    if (tid < 128){
        for (int k = 0; k < KK; k++){
            float a = __half2float(*(const __half*)(Apb + (size_t)tid*ldA + (size_t)k*2));
            for (int j = 0; j < NCOL; j++)
                facc[j] += a * __half2float(*(const __half*)(Bpb + (size_t)j*ldB + (size_t)k*2));
        }
    }
    __syncthreads();
#endif

    if (wid < 4){
        const int m = wid*32 + lid;
        const float* tmb = nullptr; const float* Xrow = nullptr;
        __half* Ch = nullptr; float* Cf = nullptr;
        if constexpr (MODE==0) Ch = (__half*)g.C + (size_t)nb*L_DIM*C_DIM + (size_t)(m0+m)*C_DIM + n0;
        if constexpr (MODE==1){
            tmb = g.tm + (size_t)nb*L_DIM + n0;
            Ch  = (__half*)g.C + (size_t)nb*C_DIM*L_DIM + (size_t)(m0+m)*L_DIM + n0;
        }
        if constexpr (MODE==2) Ch = (__half*)g.C + (size_t)nb*S_DIM*C_DIM + (size_t)(m0+m)*C_DIM + n0;
        if constexpr (MODE==5) Ch = (__half*)g.C + (size_t)nb*S_DIM*F_DIM + (size_t)(m0+m)*F_DIM + n0;
        if constexpr (MODE==6){
            Cf   = (float*)g.C + (size_t)nb*C_DIM*S_DIM + (size_t)(m0+m)*S_DIM + n0;
            Xrow = g.xa + (size_t)nb*C_DIM*S_DIM + (size_t)(m0+m)*S_DIM + n0;
        }

#pragma unroll
        for (int ch = 0; ch < NCOL/32; ch++){
            float v[32];
#if HAS_TC
            uint32_t r[32];
            LDTM32(r, tmem + (uint32_t)ch*32u);
            tc_wait_ld();
#pragma unroll
            for (int j = 0; j < 32; j++) v[j] = __uint_as_float(r[j]);
#else
            if (tid >= 128) break;
#pragma unroll
            for (int j = 0; j < 32; j++) v[j] = facc[ch*32 + j];
#endif
            if constexpr (MODE==6){
#pragma unroll
                for (int j4 = 0; j4 < 8; j4++){
                    float4 xv = *(const float4*)(Xrow + ch*32 + j4*4);
                    v[j4*4+0] += xv.x; v[j4*4+1] += xv.y; v[j4*4+2] += xv.z; v[j4*4+3] += xv.w;
                }
#pragma unroll
                for (int j4 = 0; j4 < 8; j4++)
                    *(float4*)(Cf + ch*32 + j4*4) =
                        make_float4(v[j4*4], v[j4*4+1], v[j4*4+2], v[j4*4+3]);
            } else {
                if constexpr (MODE==1){
#pragma unroll
                    for (int j = 0; j < 32; j++){ float tt = tmb[ch*32 + j]; v[j] *= tt*tt*tt; }
                }
                if constexpr (MODE==5){
#pragma unroll
                    for (int j = 0; j < 32; j++) v[j] = fmaxf(v[j], 0.f);
                }
                uint32_t pk[16];
#pragma unroll
                for (int j2 = 0; j2 < 16; j2++) pk[j2] = pack_f16(v[j2*2], v[j2*2+1]);
#pragma unroll
                for (int q = 0; q < 4; q++)
                    *(uint4*)(Ch + ch*32 + q*8) = make_uint4(pk[q*4],pk[q*4+1],pk[q*4+2],pk[q*4+3]);
            }
        }
    }
#if HAS_TC
    __syncthreads();
    if (wid == 0) tc_dealloc(tmem, NCOL);
#endif
}

template<int MODE>
__global__ void __launch_bounds__(256) tc_gemm(GP g){
    extern __shared__ char smem[];
    gemm_body<MODE>(g, blockIdx.x, blockIdx.y, blockIdx.z, smem, smem_u32(smem));
}

// fused launch for the 3 independent projection GEMMs (96 + 96 + 192 CTAs)
__global__ void __launch_bounds__(256) tc_gemm012(GP g0, GP g1, GP g2){
    extern __shared__ char smem[];
    uint32_t sb = smem_u32(smem);
    int b = blockIdx.x;
    if (b < 96)       gemm_body<0>(g0, b%6, (b/6)%8, b/48, smem, sb);
    else if (b < 192){ int c = b-96;  gemm_body<1>(g1, c%8, (c/8)%6, c/48, smem, sb); }
    else             { int c = b-192; gemm_body<2>(g2, c%3, (c/3)%32, c/96, smem, sb); }
}

// ---------------------------- fused attention kernel (fp16 operands) ----------------------------
// q/k: 2 sub-tiles of 128x64 halves (K padded 96->128 with zeros in cols 96..127).
#define AT_MB    16u
#define AT_QT    1024u                          // 2 x 16384 = 32KB
#define AT_E     (AT_QT + 32768u)               // 32KB (2 sub-tiles)
#define AT_KT(s) (AT_E + 32768u + (uint32_t)(s)*32768u)   // 2 stages x 32KB
#define AT_V3(s) (AT_E + 32768u + 65536u + (uint32_t)(s)*24576u)
#define AT_SMEM  181504u

__global__ void __launch_bounds__(256) attn_kernel(
    const __half* __restrict__ qt, const __half* __restrict__ kt,
    const __half* __restrict__ v3h,
    const float* __restrict__ im, const float* __restrict__ tm,
    const float* __restrict__ xTr, float* __restrict__ proj, __half* __restrict__ yt)
{
    extern __shared__ char smem[];
    uint32_t sb = smem_u32(smem);
    const int tid = threadIdx.x, wid = tid >> 5, lid = tid & 31;
    const int bz = blockIdx.z, nb = bz >> 3, hh = bz & 7;
    const int m0 = blockIdx.y * 128;

    const char* Aq = (const char*)(qt  + (size_t)nb*S_DIM*C_DIM + (size_t)m0*C_DIM + hh*D_DIM);
    const char* Bk = (const char*)(kt  + (size_t)nb*L_DIM*C_DIM + hh*D_DIM);
    const char* Vb = (const char*)(v3h + (size_t)nb*C_DIM*L_DIM + (size_t)hh*D_DIM*L_DIM);
    float* Pj = proj + (size_t)bz*S_DIM*L_DIM + (size_t)m0*L_DIM;

    constexpr uint32_t ID_QK = (1u<<4)|(16u<<17)|(8u<<24);  // f16, N=128
    constexpr uint32_t ID_PV = (1u<<4)|(12u<<17)|(8u<<24);  // f16, N=96
    constexpr uint32_t LDK = C_DIM*2u;   // 1536 bytes

    // hoisted fill offsets: full sub-tile (8 chunks/row) and half sub-tile (4 chunks/row, +128B src)
    uint32_t dstF[4], srcF[4], dstH[2], srcH[2], dstV[3], srcV[3];
#pragma unroll
    for (int k2 = 0; k2 < 4; k2++){
        int idx = tid + k2*256, row = idx >> 3, c4 = idx & 7;
        dstF[k2] = SWZ((uint32_t)row*128u + (uint32_t)c4*16u);
        srcF[k2] = (uint32_t)row*LDK + (uint32_t)c4*16u;
    }
#pragma unroll
    for (int k2 = 0; k2 < 2; k2++){
        int idx = tid + k2*256, row = idx >> 2, c4 = idx & 3;
        dstH[k2] = SWZ((uint32_t)row*128u + (uint32_t)c4*16u);
        srcH[k2] = (uint32_t)row*LDK + 128u + (uint32_t)c4*16u;
    }
#pragma unroll
    for (int k2 = 0; k2 < 3; k2++){
        int idx = tid + k2*256, row = idx >> 3, c4 = idx & 7;
        dstV[k2] = SWZ((uint32_t)row*128u + (uint32_t)c4*16u);
        srcV[k2] = (uint32_t)row*(L_DIM*2u) + (uint32_t)c4*16u;
    }

#if HAS_TC
    if (wid == 0) tc_alloc(sb, 512);
    if (tid == 0){
        mbar_init(sb + AT_MB,      1);   // qk buf0
        mbar_init(sb + AT_MB + 16, 1);   // qk buf1
        mbar_init(sb + AT_MB + 32, 1);   // pv
    }
    // zero-pad cols 96..127 (bytes 64..127 of sub-tile 1 rows) in Q and both K stages
    {
        uint32_t regions[3] = { AT_QT + 16384u, AT_KT(0) + 16384u, AT_KT(1) + 16384u };
#pragma unroll
        for (int rgn = 0; rgn < 3; rgn++){
#pragma unroll
            for (int k2 = 0; k2 < 2; k2++){
                int idx = tid + k2*256, row = idx >> 2, c4 = idx & 3;
                *(uint4*)(smem + regions[rgn] + SWZ((uint32_t)row*128u + 64u + (uint32_t)c4*16u))
                    = make_uint4(0,0,0,0);
            }
        }
    }
    __syncthreads();
    uint32_t tmem;
    asm volatile("ld.shared.b32 %0, [%1];" : "=r"(tmem) : "r"(sb));
    if (wid == 0) tc_relinquish();

    auto fill_kv = [&](int blk, int s){
        const char* kb = Bk + (size_t)blk*128*LDK;
        {
            const uint32_t bkt = sb + AT_KT(s);
#pragma unroll
            for (int k2 = 0; k2 < 4; k2++) cp16(bkt + dstF[k2], kb + srcF[k2]);
        }
        {
            const uint32_t bkt = sb + AT_KT(s) + 16384u;
#pragma unroll
            for (int k2 = 0; k2 < 2; k2++) cp16(bkt + dstH[k2], kb + srcH[k2]);
        }
        const char* vb = Vb + (size_t)blk*256;
#pragma unroll
        for (int t2 = 0; t2 < 2; t2++){
            const uint32_t bvt = sb + AT_V3(s) + (uint32_t)t2*12288u;
            const char* vbt = vb + t2*128;
#pragma unroll
            for (int k2 = 0; k2 < 3; k2++) cp16(bvt + dstV[k2], vbt + srcV[k2]);
        }
    };
    auto issue_qk = [&](int blk, int buf){
        if (wid == 0 && elect_one()){
            fence_proxy();
#pragma unroll
            for (int t = 0; t < 2; t++){
                uint64_t ad = mk_desc(sb + AT_QT + (uint32_t)t*16384u);
                uint64_t bd = mk_desc(sb + AT_KT(blk&1) + (uint32_t)t*16384u);
#pragma unroll
                for (int c = 0; c < 4; c++)
                    mma_f16(tmem + (uint32_t)buf*128u, ad + c*2, bd + c*2, ID_QK,
                            (t > 0 || c > 0) ? 1u : 0u);
            }
            tc_commit(sb + AT_MB + (uint32_t)buf*16u);
        }
    };
    auto issue_pv = [&](int blk){
        if (wid == 0 && elect_one()){
            fence_proxy();
#pragma unroll
            for (int t2 = 0; t2 < 2; t2++){
                uint64_t ad = mk_desc(sb + AT_E + (uint32_t)t2*16384u);
                uint64_t bd = mk_desc(sb + AT_V3(blk&1) + (uint32_t)t2*12288u);
#pragma unroll
                for (int c = 0; c < 4; c++)
                    mma_f16(tmem + 256u, ad + c*2, bd + c*2, ID_PV,
                            (blk > 0 || t2 > 0 || c > 0) ? 1u : 0u);
            }
            tc_commit(sb + AT_MB + 32u);
        }
    };

    // prologue: q tile (2 sub-tiles) + first kv stage
    {
        const uint32_t bq0 = sb + AT_QT;
#pragma unroll
        for (int k2 = 0; k2 < 4; k2++) cp16(bq0 + dstF[k2], Aq + srcF[k2]);
        const uint32_t bq1 = sb + AT_QT + 16384u;
#pragma unroll
        for (int k2 = 0; k2 < 2; k2++) cp16(bq1 + dstH[k2], Aq + srcH[k2]);
    }
    cp_commit();
    fill_kv(0, 0);
    cp_commit();
    cp_wait<0>();
    __syncthreads();
    issue_qk(0, 0);

    const int mrow = (wid & 3)*32 + lid;
    const int cbase = (wid >> 2)*64;
    const float scl = im[(size_t)nb*S_DIM + m0 + mrow] * 0.1020620726159657f;
    float rsum = 0.f;

    int phq[2] = {0,0}, php = 0;
    for (int blk = 0; blk < 8; blk++){
        if (blk > 0){ mbar_wait(sb + AT_MB + 32u, (uint32_t)php); php ^= 1; }
        if (blk + 1 < 8){ fill_kv(blk + 1, (blk + 1)&1); }
        cp_commit();

        mbar_wait(sb + AT_MB + (uint32_t)(blk&1)*16u, (uint32_t)phq[blk&1]); phq[blk&1] ^= 1;

        // issue qk(blk+1) BEFORE the convert so its MMA overlaps convert ALU work
        if (blk + 1 < 8){
            cp_wait<0>();
            __syncthreads();
            issue_qk(blk + 1, (blk + 1)&1);
        }
        fence_after();

        // convert coef tile D(blk&1): proj out, e fp16 to SMEM, denom accumulate
        {
            const float* tmb = tm + (size_t)nb*L_DIM + blk*128 + cbase;
            float* prow = Pj + (size_t)mrow*L_DIM + blk*128 + cbase;
#pragma unroll
            for (int ch = 0; ch < 2; ch++){
                uint32_t r[32];
                LDTM32(r, tmem + (uint32_t)(blk&1)*128u + (uint32_t)cbase + (uint32_t)ch*32u);
                tc_wait_ld();
                uint32_t pk[16]; float vv[32];
#pragma unroll
                for (int j2 = 0; j2 < 16; j2++){
                    float c0 = __uint_as_float(r[j2*2])   * scl;
                    float c1 = __uint_as_float(r[j2*2+1]) * scl;
                    float t0 = tmb[ch*32 + j2*2], t1 = tmb[ch*32 + j2*2+1];
                    float e0 = __expf(c0), e1 = __expf(c1);
                    rsum += e0*t0 + e1*t1;
                    pk[j2] = pack_f16(e0, e1);
                    vv[j2*2]   = c0*t0;
                    vv[j2*2+1] = c1*t1;
                }
                const int col = cbase + ch*32;
                const uint32_t t2 = (uint32_t)(col >> 6);
                const uint32_t off = (uint32_t)((col & 63) * 2);
#pragma unroll
                for (int q = 0; q < 4; q++)
                    *(uint4*)(smem + AT_E + t2*16384u + SWZ((uint32_t)mrow*128u + off + (uint32_t)q*16u))
                        = make_uint4(pk[q*4],pk[q*4+1],pk[q*4+2],pk[q*4+3]);
#pragma unroll
                for (int q = 0; q < 8; q++)
                    __stcs((float4*)(prow + ch*32 + q*4),
                           make_float4(vv[q*4], vv[q*4+1], vv[q*4+2], vv[q*4+3]));
            }
        }
        __syncthreads();
        issue_pv(blk);
    }
    mbar_wait(sb + AT_MB + 32u, (uint32_t)php);
    fence_after();

    // combine denominator halves
    float* rs = (float*)(smem + AT_E);
    rs[(wid>>2)*128 + mrow] = rsum;
    __syncthreads();

    // epilogue: xp from TMEM, scale, add x, write y_t fp16
    if (wid < 4){
        const int m = wid*32 + lid;
        const float dv = 1.f / (rs[m] + rs[128 + m] + 1e-6f);
        const float* Xrow = xTr + (size_t)nb*S_DIM*C_DIM + (size_t)(m0 + m)*C_DIM + hh*D_DIM;
        __half* Yrow = yt + (size_t)nb*S_DIM*C_DIM + (size_t)(m0 + m)*C_DIM + hh*D_DIM;
#pragma unroll
        for (int ch = 0; ch < 3; ch++){
            uint32_t r[32];
            LDTM32(r, tmem + 256u + (uint32_t)ch*32u);
            tc_wait_ld();
            uint32_t pk[16];
#pragma unroll
            for (int j2 = 0; j2 < 16; j2++){
                float a0 = __uint_as_float(r[j2*2])  *dv + Xrow[ch*32 + j2*2];
                float a1 = __uint_as_float(r[j2*2+1])*dv + Xrow[ch*32 + j2*2+1];
                pk[j2] = pack_f16(a0, a1);
            }
#pragma unroll
            for (int q = 0; q < 4; q++)
                *(uint4*)(Yrow + ch*32 + q*8) = make_uint4(pk[q*4],pk[q*4+1],pk[q*4+2],pk[q*4+3]);
        }
    }
    __syncthreads();
    if (wid == 0) tc_dealloc(tmem, 512);
#else
    // fallback (never executed on sm_103a hardware): naive but correct
    for (int m = tid; m < 128; m += 256){
        float scl = im[(size_t)nb*S_DIM + m0 + m] * 0.1020620726159657f;
        const __half* qrow = qt + (size_t)nb*S_DIM*C_DIM + (size_t)(m0+m)*C_DIM + hh*D_DIM;
        float xp[96];
#pragma unroll
        for (int d = 0; d < 96; d++) xp[d] = 0.f;
        float rsum = 0.f;
        for (int l = 0; l < L_DIM; l++){
            const __half* krow = kt + (size_t)nb*L_DIM*C_DIM + (size_t)l*C_DIM + hh*D_DIM;
            float c = 0.f;
            for (int d = 0; d < 96; d++) c += __half2float(qrow[d])*__half2float(krow[d]);
            c *= scl;
            float t = tm[(size_t)nb*L_DIM + l];
            Pj[(size_t)m*L_DIM + l] = c*t;
            float e = expf(c);
            rsum += e*t;
            float eh = __half2float(__float2half_rn(e));
            for (int d = 0; d < 96; d++)
                xp[d] += eh * __half2float(v3h[(size_t)nb*C_DIM*L_DIM + (size_t)(hh*D_DIM+d)*L_DIM + l]);
        }
        float dv = 1.f/(rsum + 1e-6f);
        for (int d = 0; d < 96; d++)
            yt[(size_t)nb*S_DIM*C_DIM + (size_t)(m0+m)*C_DIM + hh*D_DIM + d] =
                __float2half_rn(xp[d]*dv + xTr[(size_t)nb*S_DIM*C_DIM + (size_t)(m0+m)*C_DIM + hh*D_DIM + d]);
    }
#endif
}

// ---------------------------- host ----------------------------
extern "C" void kernel_launch(void* const* d_in, const int* in_sizes, int n_in,
                              void* d_out, int out_size)
{
    const float* x     = (const float*)d_in[0];
    const float* xt    = (const float*)d_in[1];
    const float* tmask = (const float*)d_in[2];
    const float* im    = (const float*)d_in[3];
    const float* Wv    = (const float*)d_in[4];
    const float* Wk    = (const float*)d_in[5];
    const float* Wq    = (const float*)d_in[6];
    const float* W1    = (const float*)d_in[7];
    const float* W2    = (const float*)d_in[8];
    float* outx = (float*)d_out;
    float* proj = outx + (size_t)NBATCH*C_DIM*S_DIM;

    float *pxTr;
    __half *pxT, *pxtT, *pqt, *pkt, *pyt, *pht, *pv3h, *pw;
    cudaGetSymbolAddress((void**)&pxTr, g_xTr);
    cudaGetSymbolAddress((void**)&pxT,  g_xT);
    cudaGetSymbolAddress((void**)&pxtT, g_xtT);
    cudaGetSymbolAddress((void**)&pqt,  g_qt);
    cudaGetSymbolAddress((void**)&pkt,  g_kt);
    cudaGetSymbolAddress((void**)&pyt,  g_yt);
    cudaGetSymbolAddress((void**)&pht,  g_ht);
    cudaGetSymbolAddress((void**)&pv3h, g_v3h);
    cudaGetSymbolAddress((void**)&pw,   g_w16);

    cudaFuncSetAttribute((const void*)tc_gemm012, cudaFuncAttributeMaxDynamicSharedMemorySize, SMEM_BYTES);
    cudaFuncSetAttribute((const void*)attn_kernel, cudaFuncAttributeMaxDynamicSharedMemorySize, AT_SMEM);
    cudaFuncSetAttribute((const void*)tc_gemm<5>, cudaFuncAttributeMaxDynamicSharedMemorySize, SMEM_BYTES);
    cudaFuncSetAttribute((const void*)tc_gemm<6>, cudaFuncAttributeMaxDynamicSharedMemorySize, SMEM_BYTES);

    // prep: both transposes + weight cvt, one launch
    prep_all<<<PREPALL_GRID, 256>>>(x, xt, Wv, Wk, Wq, W1, W2);

    GP g0 = {pxtT,        pw + WK_OFF, pkt, nullptr, nullptr};
    GP g1 = {pw + WV_OFF, pxtT,        pv3h, tmask,  nullptr};
    GP g2 = {pxT,         pw + WQ_OFF, pqt, nullptr, nullptr};
    tc_gemm012<<<384, 256, SMEM_BYTES>>>(g0, g1, g2);

    // fused attention: proj (final), y_t
    attn_kernel<<<dim3(1, S_DIM/128, NHEAD), 256, AT_SMEM>>>(
        pqt, pkt, pv3h, im, tmask, pxTr, proj, pyt);

    // hmid = relu(y_t . W1^T)   (BN=256)
    GP g5 = {pyt, pw + W1_OFF, pht, nullptr, nullptr};
    tc_gemm<5><<<dim3(F_DIM/256, S_DIM/128, NBATCH), 256, SMEM_BYTES>>>(g5);
    // out[c][s] = x + W2 . h_t^T   (BN=256)
    GP g6 = {pw + W2_OFF, pht, outx, nullptr, x};
    tc_gemm<6><<<dim3(S_DIM/256, C_DIM/128, NBATCH), 256, SMEM_BYTES>>>(g6);
}

// round 17
// speedup vs baseline: 1.0436x; 1.0436x over previous
#include <cuda_runtime.h>
#include <cuda_fp16.h>
#include <math.h>
#include <stdint.h>

// ---- arch-feature gate: tcgen05 only exists in the sm_103a/sm_100a passes ----
#if defined(__CUDA_ARCH_FEAT_SM103_ALL) || defined(__CUDA_ARCH_FEAT_SM100_ALL) || defined(__CUDA_ARCH_FEAT_SM101_ALL)
#  define HAS_TC 1
#elif defined(__CUDA_ARCH_HAS_FEATURE__)
#  if __CUDA_ARCH_HAS_FEATURE__(SM103_ALL) || __CUDA_ARCH_HAS_FEATURE__(SM100_ALL)
#    define HAS_TC 1
#  else
#    define HAS_TC 0
#  endif
#else
#  define HAS_TC 0
#endif

#define NBATCH 2
#define C_DIM  768
#define S_DIM  4096
#define L_DIM  1024
#define D_DIM  96
#define T_DIM  384
#define F_DIM  1536
#define NHEAD  16

// ------------- scratch (__device__ globals; no allocation allowed) -------------
static __device__ __align__(16) __half g_xT [NBATCH*S_DIM*C_DIM];  // x^T fp16
static __device__ __align__(16) __half g_xtT[NBATCH*L_DIM*T_DIM];  // x_t^T fp16
static __device__ __align__(16) __half g_qt [NBATCH*S_DIM*C_DIM];  // q_t fp16
static __device__ __align__(16) __half g_kt [NBATCH*L_DIM*C_DIM];  // k_t fp16
static __device__ __align__(16) __half g_yt [NBATCH*S_DIM*C_DIM];  // y^T fp16
static __device__ __align__(16) __half g_ht [NBATCH*S_DIM*F_DIM];  // relu(W1 y) fp16
static __device__ __align__(16) __half g_v3h[NBATCH*C_DIM*L_DIM];  // v*tm^3 fp16
// fp16 copies of weights, concatenated
#define WV_OFF 0
#define WK_OFF (C_DIM*T_DIM)
#define WQ_OFF (2*C_DIM*T_DIM)
#define W1_OFF (2*C_DIM*T_DIM + C_DIM*C_DIM)
#define W2_OFF (W1_OFF + 2*C_DIM*C_DIM)
#define W_TOT  (W2_OFF + 2*C_DIM*C_DIM)
static __device__ __align__(16) __half g_w16[W_TOT];

// ---------------------------- PTX helpers ----------------------------
__device__ __forceinline__ uint32_t smem_u32(const void* p){
    uint32_t a;
    asm("{ .reg .u64 t; cvta.to.shared.u64 t, %1; cvt.u32.u64 %0, t; }":"=r"(a):"l"(p));
    return a;
}
__device__ __forceinline__ uint32_t elect_one(){
    uint32_t r;
    asm volatile("{\n\t.reg .pred p;\n\telect.sync _|p, 0xFFFFFFFF;\n\tselp.b32 %0, 1, 0, p;\n\t}":"=r"(r));
    return r;
}
__device__ __forceinline__ uint32_t pack_f16(float lo, float hi){
    uint32_t r; asm("cvt.rn.f16x2.f32 %0, %1, %2;":"=r"(r):"f"(hi),"f"(lo));
    return r;
}
#define SWZ(o) ((o) ^ ((((uint32_t)(o))>>3)&0x70u))

__device__ __forceinline__ void cp16(uint32_t dst, const void* src){
    asm volatile("cp.async.cg.shared.global [%0], [%1], 16;"::"r"(dst),"l"(src):"memory");
}
__device__ __forceinline__ void cp_commit(){
    asm volatile("cp.async.commit_group;":::"memory");
}
template<int N> __device__ __forceinline__ void cp_wait(){
    asm volatile("cp.async.wait_group %0;"::"n"(N):"memory");
}
__device__ __forceinline__ void mbar_init(uint32_t a, uint32_t cnt){
    asm volatile("mbarrier.init.shared.b64 [%0], %1;"::"r"(a),"r"(cnt):"memory");
}
__device__ __forceinline__ void mbar_wait(uint32_t a, uint32_t ph){
    asm volatile(
        "{\n\t.reg .pred P;\n\t"
        "WL%=:\n\t"
        "mbarrier.try_wait.parity.acquire.cta.shared::cta.b64 P, [%0], %1;\n\t"
        "@P bra WD%=;\n\t"
        "bra WL%=;\n\t"
        "WD%=:\n\t}"
        ::"r"(a),"r"(ph):"memory");
}
__device__ __forceinline__ void tc_commit(uint32_t mb){
#if HAS_TC
    asm volatile("tcgen05.commit.cta_group::1.mbarrier::arrive::one.shared::cluster.b64 [%0];"
                 ::"r"(mb):"memory");
#endif
}
__device__ __forceinline__ void tc_alloc(uint32_t smem_dst, uint32_t ncols){
#if HAS_TC
    asm volatile("tcgen05.alloc.cta_group::1.sync.aligned.shared::cta.b32 [%0], %1;"
                 ::"r"(smem_dst),"r"(ncols):"memory");
#endif
}
__device__ __forceinline__ void tc_dealloc(uint32_t tmem, uint32_t ncols){
#if HAS_TC
    asm volatile("tcgen05.dealloc.cta_group::1.sync.aligned.b32 %0, %1;"::"r"(tmem),"r"(ncols));
#endif
}
__device__ __forceinline__ void tc_relinquish(){
#if HAS_TC
    asm volatile("tcgen05.relinquish_alloc_permit.cta_group::1.sync.aligned;");
#endif
}
__device__ __forceinline__ void fence_after(){
#if HAS_TC
    asm volatile("tcgen05.fence::after_thread_sync;":::"memory");
#endif
}
__device__ __forceinline__ void fence_proxy(){
    asm volatile("fence.proxy.async.shared::cta;":::"memory");
}
__device__ __forceinline__ void tc_wait_ld(){
#if HAS_TC
    asm volatile("tcgen05.wait::ld.sync.aligned;":::"memory");
#endif
}
__device__ __forceinline__ uint64_t mk_desc(uint32_t addr){
    const uint64_t BASE = (uint64_t(2)<<61)|(uint64_t(1)<<46)|(uint64_t(64)<<32)|(uint64_t(1)<<16);
    return BASE | ((uint64_t)(addr>>4) & 0x3FFFull);
}
// fp16 MMA (kind::f16, atype=btype=F16=0, dtype=F32)
__device__ __forceinline__ void mma_f16(uint32_t d, uint64_t ad, uint64_t bd, uint32_t idesc, uint32_t en){
#if HAS_TC
    asm volatile(
        "{\n\t.reg .pred p;\n\tsetp.ne.u32 p, %5, 0;\n\t"
        "tcgen05.mma.cta_group::1.kind::f16 [%0], %1, %2, %3, {%4,%4,%4,%4}, p;\n\t}"
        :: "r"(d), "l"(ad), "l"(bd), "r"(idesc), "r"(0u), "r"(en) : "memory");
#endif
}
#if HAS_TC
#define LDTM32(r, a) \
    asm volatile( \
        "tcgen05.ld.sync.aligned.32x32b.x32.b32 " \
        "{%0, %1, %2, %3, %4, %5, %6, %7, " \
        " %8, %9, %10, %11, %12, %13, %14, %15, " \
        " %16, %17, %18, %19, %20, %21, %22, %23, " \
        " %24, %25, %26, %27, %28, %29, %30, %31}, [%32];" \
        : "=r"((r)[0]),  "=r"((r)[1]),  "=r"((r)[2]),  "=r"((r)[3]), \
          "=r"((r)[4]),  "=r"((r)[5]),  "=r"((r)[6]),  "=r"((r)[7]), \
          "=r"((r)[8]),  "=r"((r)[9]),  "=r"((r)[10]), "=r"((r)[11]), \
          "=r"((r)[12]), "=r"((r)[13]), "=r"((r)[14]), "=r"((r)[15]), \
          "=r"((r)[16]), "=r"((r)[17]), "=r"((r)[18]), "=r"((r)[19]), \
          "=r"((r)[20]), "=r"((r)[21]), "=r"((r)[22]), "=r"((r)[23]), \
          "=r"((r)[24]), "=r"((r)[25]), "=r"((r)[26]), "=r"((r)[27]), \
          "=r"((r)[28]), "=r"((r)[29]), "=r"((r)[30]), "=r"((r)[31]) \
        : "r"(a))
#endif

// ---------------------------- prep (fused transposes + cvt) ----------------------------
__device__ __forceinline__ void transpose_body(const float* __restrict__ src,
                                               __half* __restrict__ dst16,
                                               int R, int Cc, int bx, int by, int nb, int tid){
    __shared__ float t[32][33];
    src   += (size_t)nb*R*Cc;
    dst16 += (size_t)nb*R*Cc;
    int c0 = bx*32, r0 = by*32;
    int x = tid & 31, y = tid >> 5;
#pragma unroll
    for (int i = 0; i < 32; i += 8)
        t[y+i][x] = src[(size_t)(r0+y+i)*Cc + c0 + x];
    __syncthreads();
#pragma unroll
    for (int i = 0; i < 32; i += 8)
        dst16[(size_t)(c0+y+i)*R + r0 + x] = __float2half_rn(t[x][y+i]);
}

#define TRX_BLKS  (S_DIM/32 * C_DIM/32 * NBATCH)   // 6144
#define TRXT_BLKS (L_DIM/32 * T_DIM/32 * NBATCH)   // 768
#define PREP_TOTAL (2*(C_DIM*T_DIM/4) + C_DIM*C_DIM/4 + 2*(2*C_DIM*C_DIM/4))
#define PREP_BLKS ((PREP_TOTAL + 255)/256)
#define PREPALL_GRID (TRX_BLKS + TRXT_BLKS + PREP_BLKS)

__global__ void __launch_bounds__(256) prep_all(
    const float* __restrict__ x, const float* __restrict__ xt,
    const float* __restrict__ Wv, const float* __restrict__ Wk, const float* __restrict__ Wq,
    const float* __restrict__ W1, const float* __restrict__ W2)
{
    int b = blockIdx.x, tid = threadIdx.x;
    if (b < TRX_BLKS){
        transpose_body(x, g_xT, C_DIM, S_DIM, b % (S_DIM/32),
                       (b/(S_DIM/32)) % (C_DIM/32), b/(S_DIM/32 * C_DIM/32), tid);
        return;
    }
    b -= TRX_BLKS;
    if (b < TRXT_BLKS){
        transpose_body(xt, g_xtT, T_DIM, L_DIM, b % (L_DIM/32),
                       (b/(L_DIM/32)) % (T_DIM/32), b/(L_DIM/32 * T_DIM/32), tid);
        return;
    }
    b -= TRXT_BLKS;
    int j = b*256 + tid;
    const int NVT = C_DIM*T_DIM/4, NQ = C_DIM*C_DIM/4, NF = 2*C_DIM*C_DIM/4;
    const float* src; __half* dst;
    if (j < NVT){ src = Wv; dst = g_w16 + WV_OFF; }
    else if ((j -= NVT) < NVT){ src = Wk; dst = g_w16 + WK_OFF; }
    else if ((j -= NVT) < NQ ){ src = Wq; dst = g_w16 + WQ_OFF; }
    else if ((j -= NQ ) < NF ){ src = W1; dst = g_w16 + W1_OFF; }
    else if ((j -= NF ) < NF ){ src = W2; dst = g_w16 + W2_OFF; }
    else return;
    float4 v = ((const float4*)src)[j];
    uint2 o;
    o.x = pack_f16(v.x, v.y);
    o.y = pack_f16(v.z, v.w);
    ((uint2*)dst)[j] = o;
}

// ---------------------------- generic tcgen05 fp16 GEMM ----------------------------
// BN=128, K-tile=64 halves (128B rows), 2 stages distance-1, 65KB SMEM -> 3 CTAs/SM.
#define SM_TMEM 0
#define SM_MB   16
#define SM_A(s) (1024u  + (uint32_t)(s)*16384u)
#define SM_B(s) (33792u + (uint32_t)(s)*16384u)
#define SMEM_BYTES 66560

struct GP {
    const void* A; const void* B; void* C;
    const float* tm; const float* xa;
};

template<int MODE>
__device__ __forceinline__ void gemm_body(const GP& g, int bxx, int byy, int nb,
                                          char* smem, uint32_t sb)
{
    const int tid = threadIdx.x, wid = tid >> 5, lid = tid & 31;
    const int m0 = byy*128, n0 = bxx*128;
    constexpr int KK = (MODE==0||MODE==1) ? T_DIM : (MODE==2||MODE==5) ? C_DIM : F_DIM;
    constexpr int NT = KK / 64;
    constexpr uint32_t IDESC = (1u<<4)|(16u<<17)|(8u<<24);   // f16 in, f32 acc, N=128, M=128

    const char* Apb = nullptr; const char* Bpb = nullptr;
    uint32_t ldA = 0, ldB = 0;
    if constexpr (MODE==0){ Apb=(const char*)g.A + ((size_t)nb*L_DIM*T_DIM+(size_t)m0*T_DIM)*2; ldA=T_DIM*2;
                            Bpb=(const char*)g.B + (size_t)n0*T_DIM*2; ldB=T_DIM*2; }
    if constexpr (MODE==1){ Apb=(const char*)g.A + (size_t)m0*T_DIM*2; ldA=T_DIM*2;
                            Bpb=(const char*)g.B + ((size_t)nb*L_DIM*T_DIM+(size_t)n0*T_DIM)*2; ldB=T_DIM*2; }
    if constexpr (MODE==2){ Apb=(const char*)g.A + ((size_t)nb*S_DIM*C_DIM+(size_t)m0*C_DIM)*2; ldA=C_DIM*2;
                            Bpb=(const char*)g.B + (size_t)n0*C_DIM*2; ldB=C_DIM*2; }
    if constexpr (MODE==5){ Apb=(const char*)g.A + ((size_t)nb*S_DIM*C_DIM+(size_t)m0*C_DIM)*2; ldA=C_DIM*2;
                            Bpb=(const char*)g.B + (size_t)n0*C_DIM*2; ldB=C_DIM*2; }
    if constexpr (MODE==6){ Apb=(const char*)g.A + (size_t)m0*F_DIM*2; ldA=F_DIM*2;
                            Bpb=(const char*)g.B + ((size_t)nb*S_DIM*F_DIM+(size_t)n0*F_DIM)*2; ldB=F_DIM*2; }

    // hoisted per-thread fill offsets (loop-invariant)
    uint32_t dstOff[4], srcAOff[4], srcBOff[4];
#pragma unroll
    for (int k2 = 0; k2 < 4; k2++){
        int idx = tid + k2*256, row = idx >> 3, c4 = idx & 7;
        dstOff[k2]  = SWZ((uint32_t)row*128u + (uint32_t)c4*16u);
        srcAOff[k2] = (uint32_t)row*ldA + (uint32_t)c4*16u;
        srcBOff[k2] = (uint32_t)row*ldB + (uint32_t)c4*16u;
    }
    auto fill_tile = [&](int tt, int s){
        const char* a = Apb + (size_t)tt*128;
        const char* b = Bpb + (size_t)tt*128;
        const uint32_t ba = sb + SM_A(s), bb = sb + SM_B(s);
#pragma unroll
        for (int k2 = 0; k2 < 4; k2++) cp16(ba + dstOff[k2], a + srcAOff[k2]);
#pragma unroll
        for (int k2 = 0; k2 < 4; k2++) cp16(bb + dstOff[k2], b + srcBOff[k2]);
    };

#if HAS_TC
    if (wid == 0) tc_alloc(sb + SM_TMEM, 128);
    if (tid == 0){
        mbar_init(sb + SM_MB,      1);
        mbar_init(sb + SM_MB + 16, 1);
    }
    __syncthreads();
    uint32_t tmem;
    asm volatile("ld.shared.b32 %0, [%1];" : "=r"(tmem) : "r"(sb + SM_TMEM));
    if (wid == 0) tc_relinquish();

    int ph[2] = {0,0};
    fill_tile(0, 0); cp_commit();

    for (int t = 0; t < NT; t++){
        const int nf = t + 1;
        if (nf < NT){
            const int s = nf & 1;
            if (nf >= 2){ mbar_wait(sb + SM_MB + (uint32_t)s*16u, (uint32_t)ph[s]); ph[s] ^= 1; }
            fill_tile(nf, s);
        }
        cp_commit();
        cp_wait<1>();
        __syncthreads();
        const int sc = t & 1;
        if (wid == 0 && elect_one()){
            fence_proxy();
            uint64_t ad = mk_desc(sb + SM_A(sc));
            uint64_t bd = mk_desc(sb + SM_B(sc));
#pragma unroll
            for (int c = 0; c < 4; c++)           // 4 x K=16 per 64-K tile
                mma_f16(tmem, ad + c*2, bd + c*2, IDESC, (t > 0 || c > 0) ? 1u : 0u);
            tc_commit(sb + SM_MB + (uint32_t)sc*16u);
        }
    }
    {
        const int sl = (NT - 1) & 1;
        mbar_wait(sb + SM_MB + (uint32_t)sl*16u, (uint32_t)ph[sl]);
    }
    fence_after();
#else
    float facc[128];
#pragma unroll
    for (int j = 0; j < 128; j++) facc[j] = 0.f;
    if (tid < 128){
        for (int k = 0; k < KK; k++){
            float a = __half2float(*(const __half*)(Apb + (size_t)tid*ldA + (size_t)k*2));
            for (int j = 0; j < 128; j++)
                facc[j] += a * __half2float(*(const __half*)(Bpb + (size_t)j*ldB + (size_t)k*2));
        }
    }
    __syncthreads();
#endif

    if (wid < 4){
        const int m = wid*32 + lid;
        const float* tmb = nullptr; const float* Xrow = nullptr;
        __half* Ch = nullptr; float* Cf = nullptr;
        if constexpr (MODE==0) Ch = (__half*)g.C + (size_t)nb*L_DIM*C_DIM + (size_t)(m0+m)*C_DIM + n0;
        if constexpr (MODE==1){
            tmb = g.tm + (size_t)nb*L_DIM + n0;
            Ch  = (__half*)g.C + (size_t)nb*C_DIM*L_DIM + (size_t)(m0+m)*L_DIM + n0;
        }
        if constexpr (MODE==2) Ch = (__half*)g.C + (size_t)nb*S_DIM*C_DIM + (size_t)(m0+m)*C_DIM + n0;
        if constexpr (MODE==5) Ch = (__half*)g.C + (size_t)nb*S_DIM*F_DIM + (size_t)(m0+m)*F_DIM + n0;
        if constexpr (MODE==6){
            Cf   = (float*)g.C + (size_t)nb*C_DIM*S_DIM + (size_t)(m0+m)*S_DIM + n0;
            Xrow = g.xa + (size_t)nb*C_DIM*S_DIM + (size_t)(m0+m)*S_DIM + n0;
        }

#pragma unroll
        for (int ch = 0; ch < 4; ch++){
            float v[32];
#if HAS_TC
            uint32_t r[32];
            LDTM32(r, tmem + (uint32_t)ch*32u);
            tc_wait_ld();
#pragma unroll
            for (int j = 0; j < 32; j++) v[j] = __uint_as_float(r[j]);
#else
            if (tid >= 128) break;
#pragma unroll
            for (int j = 0; j < 32; j++) v[j] = facc[ch*32 + j];
#endif
            if constexpr (MODE==6){
#pragma unroll
                for (int j4 = 0; j4 < 8; j4++){
                    float4 xv = *(const float4*)(Xrow + ch*32 + j4*4);
                    v[j4*4+0] += xv.x; v[j4*4+1] += xv.y; v[j4*4+2] += xv.z; v[j4*4+3] += xv.w;
                }
#pragma unroll
                for (int j4 = 0; j4 < 8; j4++)
                    *(float4*)(Cf + ch*32 + j4*4) =
                        make_float4(v[j4*4], v[j4*4+1], v[j4*4+2], v[j4*4+3]);
            } else {
                if constexpr (MODE==1){
#pragma unroll
                    for (int j = 0; j < 32; j++){ float tt = tmb[ch*32 + j]; v[j] *= tt*tt*tt; }
                }
                if constexpr (MODE==5){
#pragma unroll
                    for (int j = 0; j < 32; j++) v[j] = fmaxf(v[j], 0.f);
                }
                uint32_t pk[16];
#pragma unroll
                for (int j2 = 0; j2 < 16; j2++) pk[j2] = pack_f16(v[j2*2], v[j2*2+1]);
#pragma unroll
                for (int q = 0; q < 4; q++)
                    *(uint4*)(Ch + ch*32 + q*8) = make_uint4(pk[q*4],pk[q*4+1],pk[q*4+2],pk[q*4+3]);
            }
        }
    }
#if HAS_TC
    __syncthreads();
    if (wid == 0) tc_dealloc(tmem, 128);
#endif
}

template<int MODE>
__global__ void __launch_bounds__(256) tc_gemm(GP g){
    extern __shared__ char smem[];
    gemm_body<MODE>(g, blockIdx.x, blockIdx.y, blockIdx.z, smem, smem_u32(smem));
}

// fused launch for the 3 independent projection GEMMs (96 + 96 + 384 CTAs)
__global__ void __launch_bounds__(256) tc_gemm012(GP g0, GP g1, GP g2){
    extern __shared__ char smem[];
    uint32_t sb = smem_u32(smem);
    int b = blockIdx.x;
    if (b < 96)       gemm_body<0>(g0, b%6, (b/6)%8, b/48, smem, sb);
    else if (b < 192){ int c = b-96;  gemm_body<1>(g1, c%8, (c/8)%6, c/48,  smem, sb); }
    else             { int c = b-192; gemm_body<2>(g2, c%6, (c/6)%32, c/192, smem, sb); }
}

// ---------------------------- fused attention kernel (fp16 operands) ----------------------------
// q/k: 2 sub-tiles of 128x64 halves (K padded 96->128 with zeros in cols 96..127).
#define AT_MB    16u
#define AT_QT    1024u                          // 2 x 16384 = 32KB
#define AT_E     (AT_QT + 32768u)               // 32KB (2 sub-tiles)
#define AT_KT(s) (AT_E + 32768u + (uint32_t)(s)*32768u)   // 2 stages x 32KB
#define AT_V3(s) (AT_E + 32768u + 65536u + (uint32_t)(s)*24576u)
#define AT_SMEM  181504u

__global__ void __launch_bounds__(256) attn_kernel(
    const __half* __restrict__ qt, const __half* __restrict__ kt,
    const __half* __restrict__ v3h,
    const float* __restrict__ im, const float* __restrict__ tm,
    const __half* __restrict__ xTh, float* __restrict__ proj, __half* __restrict__ yt)
{
    extern __shared__ char smem[];
    uint32_t sb = smem_u32(smem);
    const int tid = threadIdx.x, wid = tid >> 5, lid = tid & 31;
    const int bz = blockIdx.z, nb = bz >> 3, hh = bz & 7;
    const int m0 = blockIdx.y * 128;

    const char* Aq = (const char*)(qt  + (size_t)nb*S_DIM*C_DIM + (size_t)m0*C_DIM + hh*D_DIM);
    const char* Bk = (const char*)(kt  + (size_t)nb*L_DIM*C_DIM + hh*D_DIM);
    const char* Vb = (const char*)(v3h + (size_t)nb*C_DIM*L_DIM + (size_t)hh*D_DIM*L_DIM);
    float* Pj = proj + (size_t)bz*S_DIM*L_DIM + (size_t)m0*L_DIM;

    constexpr uint32_t ID_QK = (1u<<4)|(16u<<17)|(8u<<24);  // f16, N=128
    constexpr uint32_t ID_PV = (1u<<4)|(12u<<17)|(8u<<24);  // f16, N=96
    constexpr uint32_t LDK = C_DIM*2u;   // 1536 bytes

    // hoisted fill offsets: full sub-tile (8 chunks/row) and half sub-tile (4 chunks/row, +128B src)
    uint32_t dstF[4], srcF[4], dstH[2], srcH[2], dstV[3], srcV[3];
#pragma unroll
    for (int k2 = 0; k2 < 4; k2++){
        int idx = tid + k2*256, row = idx >> 3, c4 = idx & 7;
        dstF[k2] = SWZ((uint32_t)row*128u + (uint32_t)c4*16u);
        srcF[k2] = (uint32_t)row*LDK + (uint32_t)c4*16u;
    }
#pragma unroll
    for (int k2 = 0; k2 < 2; k2++){
        int idx = tid + k2*256, row = idx >> 2, c4 = idx & 3;
        dstH[k2] = SWZ((uint32_t)row*128u + (uint32_t)c4*16u);
        srcH[k2] = (uint32_t)row*LDK + 128u + (uint32_t)c4*16u;
    }
#pragma unroll
    for (int k2 = 0; k2 < 3; k2++){
        int idx = tid + k2*256, row = idx >> 3, c4 = idx & 7;
        dstV[k2] = SWZ((uint32_t)row*128u + (uint32_t)c4*16u);
        srcV[k2] = (uint32_t)row*(L_DIM*2u) + (uint32_t)c4*16u;
    }

#if HAS_TC
    if (wid == 0) tc_alloc(sb, 512);
    if (tid == 0){
        mbar_init(sb + AT_MB,      1);   // qk buf0
        mbar_init(sb + AT_MB + 16, 1);   // qk buf1
        mbar_init(sb + AT_MB + 32, 1);   // pv
    }
    // zero-pad cols 96..127 (bytes 64..127 of sub-tile 1 rows) in Q and both K stages
    {
        uint32_t regions[3] = { AT_QT + 16384u, AT_KT(0) + 16384u, AT_KT(1) + 16384u };
#pragma unroll
        for (int rgn = 0; rgn < 3; rgn++){
#pragma unroll
            for (int k2 = 0; k2 < 2; k2++){
                int idx = tid + k2*256, row = idx >> 2, c4 = idx & 3;
                *(uint4*)(smem + regions[rgn] + SWZ((uint32_t)row*128u + 64u + (uint32_t)c4*16u))
                    = make_uint4(0,0,0,0);
            }
        }
    }
    __syncthreads();
    uint32_t tmem;
    asm volatile("ld.shared.b32 %0, [%1];" : "=r"(tmem) : "r"(sb));
    if (wid == 0) tc_relinquish();

    auto fill_kv = [&](int blk, int s){
        const char* kb = Bk + (size_t)blk*128*LDK;
        {
            const uint32_t bkt = sb + AT_KT(s);
#pragma unroll
            for (int k2 = 0; k2 < 4; k2++) cp16(bkt + dstF[k2], kb + srcF[k2]);
        }
        {
            const uint32_t bkt = sb + AT_KT(s) + 16384u;
#pragma unroll
            for (int k2 = 0; k2 < 2; k2++) cp16(bkt + dstH[k2], kb + srcH[k2]);
        }
        const char* vb = Vb + (size_t)blk*256;
#pragma unroll
        for (int t2 = 0; t2 < 2; t2++){
            const uint32_t bvt = sb + AT_V3(s) + (uint32_t)t2*12288u;
            const char* vbt = vb + t2*128;
#pragma unroll
            for (int k2 = 0; k2 < 3; k2++) cp16(bvt + dstV[k2], vbt + srcV[k2]);
        }
    };
    auto issue_qk = [&](int blk, int buf){
        if (wid == 0 && elect_one()){
            fence_proxy();
#pragma unroll
            for (int t = 0; t < 2; t++){
                uint64_t ad = mk_desc(sb + AT_QT + (uint32_t)t*16384u);
                uint64_t bd = mk_desc(sb + AT_KT(blk&1) + (uint32_t)t*16384u);
#pragma unroll
                for (int c = 0; c < 4; c++)
                    mma_f16(tmem + (uint32_t)buf*128u, ad + c*2, bd + c*2, ID_QK,
                            (t > 0 || c > 0) ? 1u : 0u);
            }
            tc_commit(sb + AT_MB + (uint32_t)buf*16u);
        }
    };
    auto issue_pv = [&](int blk){
        if (wid == 0 && elect_one()){
            fence_proxy();
#pragma unroll
            for (int t2 = 0; t2 < 2; t2++){
                uint64_t ad = mk_desc(sb + AT_E + (uint32_t)t2*16384u);
                uint64_t bd = mk_desc(sb + AT_V3(blk&1) + (uint32_t)t2*12288u);
#pragma unroll
                for (int c = 0; c < 4; c++)
                    mma_f16(tmem + 256u, ad + c*2, bd + c*2, ID_PV,
                            (blk > 0 || t2 > 0 || c > 0) ? 1u : 0u);
            }
            tc_commit(sb + AT_MB + 32u);
        }
    };

    // prologue: q tile (2 sub-tiles) + first kv stage
    {
        const uint32_t bq0 = sb + AT_QT;
#pragma unroll
        for (int k2 = 0; k2 < 4; k2++) cp16(bq0 + dstF[k2], Aq + srcF[k2]);
        const uint32_t bq1 = sb + AT_QT + 16384u;
#pragma unroll
        for (int k2 = 0; k2 < 2; k2++) cp16(bq1 + dstH[k2], Aq + srcH[k2]);
    }
    cp_commit();
    fill_kv(0, 0);
    cp_commit();
    cp_wait<0>();
    __syncthreads();
    issue_qk(0, 0);

    const int mrow = (wid & 3)*32 + lid;
    const int cbase = (wid >> 2)*64;
    const float scl = im[(size_t)nb*S_DIM + m0 + mrow] * 0.1020620726159657f;
    float rsum = 0.f;

    int phq[2] = {0,0}, php = 0;
    for (int blk = 0; blk < 8; blk++){
        if (blk > 0){ mbar_wait(sb + AT_MB + 32u, (uint32_t)php); php ^= 1; }
        if (blk + 1 < 8){ fill_kv(blk + 1, (blk + 1)&1); }
        cp_commit();

        mbar_wait(sb + AT_MB + (uint32_t)(blk&1)*16u, (uint32_t)phq[blk&1]); phq[blk&1] ^= 1;

        // issue qk(blk+1) BEFORE the convert so its MMA overlaps convert ALU work
        if (blk + 1 < 8){
            cp_wait<0>();
            __syncthreads();
            issue_qk(blk + 1, (blk + 1)&1);
        }
        fence_after();

        // convert coef tile D(blk&1): proj out, e fp16 to SMEM, denom accumulate
        {
            const float* tmb = tm + (size_t)nb*L_DIM + blk*128 + cbase;
            float* prow = Pj + (size_t)mrow*L_DIM + blk*128 + cbase;
#pragma unroll
            for (int ch = 0; ch < 2; ch++){
                uint32_t r[32];
                LDTM32(r, tmem + (uint32_t)(blk&1)*128u + (uint32_t)cbase + (uint32_t)ch*32u);
                tc_wait_ld();
                uint32_t pk[16]; float vv[32];
#pragma unroll
                for (int j2 = 0; j2 < 16; j2++){
                    float c0 = __uint_as_float(r[j2*2])   * scl;
                    float c1 = __uint_as_float(r[j2*2+1]) * scl;
                    float t0 = tmb[ch*32 + j2*2], t1 = tmb[ch*32 + j2*2+1];
                    float e0 = __expf(c0), e1 = __expf(c1);
                    rsum += e0*t0 + e1*t1;
                    pk[j2] = pack_f16(e0, e1);
                    vv[j2*2]   = c0*t0;
                    vv[j2*2+1] = c1*t1;
                }
                const int col = cbase + ch*32;
                const uint32_t t2 = (uint32_t)(col >> 6);
                const uint32_t off = (uint32_t)((col & 63) * 2);
#pragma unroll
                for (int q = 0; q < 4; q++)
                    *(uint4*)(smem + AT_E + t2*16384u + SWZ((uint32_t)mrow*128u + off + (uint32_t)q*16u))
                        = make_uint4(pk[q*4],pk[q*4+1],pk[q*4+2],pk[q*4+3]);
#pragma unroll
                for (int q = 0; q < 8; q++)
                    __stcs((float4*)(prow + ch*32 + q*4),
                           make_float4(vv[q*4], vv[q*4+1], vv[q*4+2], vv[q*4+3]));
            }
        }
        __syncthreads();
        issue_pv(blk);
    }
    mbar_wait(sb + AT_MB + 32u, (uint32_t)php);
    fence_after();

    // combine denominator halves
    float* rs = (float*)(smem + AT_E);
    rs[(wid>>2)*128 + mrow] = rsum;
    __syncthreads();

    // epilogue: xp from TMEM, scale, add x (fp16 residual), write y_t fp16
    if (wid < 4){
        const int m = wid*32 + lid;
        const float dv = 1.f / (rs[m] + rs[128 + m] + 1e-6f);
        const __half* Xrow = xTh + (size_t)nb*S_DIM*C_DIM + (size_t)(m0 + m)*C_DIM + hh*D_DIM;
        __half* Yrow = yt + (size_t)nb*S_DIM*C_DIM + (size_t)(m0 + m)*C_DIM + hh*D_DIM;
#pragma unroll
        for (int ch = 0; ch < 3; ch++){
            uint32_t r[32];
            LDTM32(r, tmem + 256u + (uint32_t)ch*32u);
            tc_wait_ld();
            uint32_t pk[16];
#pragma unroll
            for (int j2 = 0; j2 < 16; j2++){
                float a0 = __uint_as_float(r[j2*2])  *dv + __half2float(Xrow[ch*32 + j2*2]);
                float a1 = __uint_as_float(r[j2*2+1])*dv + __half2float(Xrow[ch*32 + j2*2+1]);
                pk[j2] = pack_f16(a0, a1);
            }
#pragma unroll
            for (int q = 0; q < 4; q++)
                *(uint4*)(Yrow + ch*32 + q*8) = make_uint4(pk[q*4],pk[q*4+1],pk[q*4+2],pk[q*4+3]);
        }
    }
    __syncthreads();
    if (wid == 0) tc_dealloc(tmem, 512);
#else
    // fallback (never executed on sm_103a hardware): naive but correct
    for (int m = tid; m < 128; m += 256){
        float scl = im[(size_t)nb*S_DIM + m0 + m] * 0.1020620726159657f;
        const __half* qrow = qt + (size_t)nb*S_DIM*C_DIM + (size_t)(m0+m)*C_DIM + hh*D_DIM;
        float xp[96];
#pragma unroll
        for (int d = 0; d < 96; d++) xp[d] = 0.f;
        float rsum = 0.f;
        for (int l = 0; l < L_DIM; l++){
            const __half* krow = kt + (size_t)nb*L_DIM*C_DIM + (size_t)l*C_DIM + hh*D_DIM;
            float c = 0.f;
            for (int d = 0; d < 96; d++) c += __half2float(qrow[d])*__half2float(krow[d]);
            c *= scl;
            float t = tm[(size_t)nb*L_DIM + l];
            Pj[(size_t)m*L_DIM + l] = c*t;
            float e = expf(c);
            rsum += e*t;
            float eh = __half2float(__float2half_rn(e));
            for (int d = 0; d < 96; d++)
                xp[d] += eh * __half2float(v3h[(size_t)nb*C_DIM*L_DIM + (size_t)(hh*D_DIM+d)*L_DIM + l]);
        }
        float dv = 1.f/(rsum + 1e-6f);
        for (int d = 0; d < 96; d++)
            yt[(size_t)nb*S_DIM*C_DIM + (size_t)(m0+m)*C_DIM + hh*D_DIM + d] =
                __float2half_rn(xp[d]*dv + __half2float(xTh[(size_t)nb*S_DIM*C_DIM + (size_t)(m0+m)*C_DIM + hh*D_DIM + d]));
    }
#endif
}

// ---------------------------- host ----------------------------
extern "C" void kernel_launch(void* const* d_in, const int* in_sizes, int n_in,
                              void* d_out, int out_size)
{
    const float* x     = (const float*)d_in[0];
    const float* xt    = (const float*)d_in[1];
    const float* tmask = (const float*)d_in[2];
    const float* im    = (const float*)d_in[3];
    const float* Wv    = (const float*)d_in[4];
    const float* Wk    = (const float*)d_in[5];
    const float* Wq    = (const float*)d_in[6];
    const float* W1    = (const float*)d_in[7];
    const float* W2    = (const float*)d_in[8];
    float* outx = (float*)d_out;
    float* proj = outx + (size_t)NBATCH*C_DIM*S_DIM;

    __half *pxT, *pxtT, *pqt, *pkt, *pyt, *pht, *pv3h, *pw;
    cudaGetSymbolAddress((void**)&pxT,  g_xT);
    cudaGetSymbolAddress((void**)&pxtT, g_xtT);
    cudaGetSymbolAddress((void**)&pqt,  g_qt);
    cudaGetSymbolAddress((void**)&pkt,  g_kt);
    cudaGetSymbolAddress((void**)&pyt,  g_yt);
    cudaGetSymbolAddress((void**)&pht,  g_ht);
    cudaGetSymbolAddress((void**)&pv3h, g_v3h);
    cudaGetSymbolAddress((void**)&pw,   g_w16);

    cudaFuncSetAttribute((const void*)tc_gemm012, cudaFuncAttributeMaxDynamicSharedMemorySize, SMEM_BYTES);
    cudaFuncSetAttribute((const void*)attn_kernel, cudaFuncAttributeMaxDynamicSharedMemorySize, AT_SMEM);
    cudaFuncSetAttribute((const void*)tc_gemm<5>, cudaFuncAttributeMaxDynamicSharedMemorySize, SMEM_BYTES);
    cudaFuncSetAttribute((const void*)tc_gemm<6>, cudaFuncAttributeMaxDynamicSharedMemorySize, SMEM_BYTES);

    // prep: both transposes + weight cvt, one launch
    prep_all<<<PREPALL_GRID, 256>>>(x, xt, Wv, Wk, Wq, W1, W2);

    GP g0 = {pxtT,        pw + WK_OFF, pkt, nullptr, nullptr};
    GP g1 = {pw + WV_OFF, pxtT,        pv3h, tmask,  nullptr};
    GP g2 = {pxT,         pw + WQ_OFF, pqt, nullptr, nullptr};
    tc_gemm012<<<576, 256, SMEM_BYTES>>>(g0, g1, g2);

    // fused attention: proj (final), y_t
    attn_kernel<<<dim3(1, S_DIM/128, NHEAD), 256, AT_SMEM>>>(
        pqt, pkt, pv3h, im, tmask, pxT, proj, pyt);

    // hmid = relu(y_t . W1^T)
    GP g5 = {pyt, pw + W1_OFF, pht, nullptr, nullptr};
    tc_gemm<5><<<dim3(F_DIM/128, S_DIM/128, NBATCH), 256, SMEM_BYTES>>>(g5);
    // out[c][s] = x + W2 . h_t^T
    GP g6 = {pw + W2_OFF, pht, outx, nullptr, x};
    tc_gemm<6><<<dim3(S_DIM/128, C_DIM/128, NBATCH), 256, SMEM_BYTES>>>(g6);
}